// round 2
// baseline (speedup 1.0000x reference)
#include <cuda_runtime.h>
#include <cstdint>
#include <math.h>

#define NW 2048
#define TCC 12
#define TSS 4
#define HHd 128
#define Hd  256
#define Gd  512
#define WXD 768

// ---------------- scratch (device globals; no allocation) ----------------
__device__ float g_X[TCC][NW][64];        // char/syl embeddings, t-major
__device__ float g_P[2][TCC][NW][Gd];     // input projections per direction
__device__ float g_h[2][NW][HHd];
__device__ float g_c[2][NW][HHd];
__device__ float g_gates[2][NW][Gd];
__device__ float g_out[TCC][NW][Hd];      // bilstm outputs
__device__ float g_E[TCC][NW][Hd];        // attention energies (pre-tanh)
__device__ float g_score[TCC][NW];
__device__ float g_wordx[NW][WXD];        // [word_emb | char_ctx | syl_ctx]
__device__ float g_PW[2][NW][Gd];         // word LSTM input projections
__device__ float g_wout[NW][Hd];

__device__ __forceinline__ float sigf(float x){ return 1.f/(1.f+expf(-x)); }

// ---------------- gather kernels ----------------
__global__ void k_gatherX(const int* __restrict__ ids, const float* __restrict__ emb, int T){
    int idx = blockIdx.x*256 + threadIdx.x;
    int total = NW*T*64;
    if (idx >= total) return;
    int dcol = idx & 63;
    int r = idx >> 6;              // w*T + t
    int t = r % T, w = r / T;
    g_X[t][w][dcol] = emb[(size_t)ids[r]*64 + dcol];
}

__global__ void k_init(const int* __restrict__ feat, const float* __restrict__ embp){
    int idx = blockIdx.x*256 + threadIdx.x;   // 2*NW*HH = 524288
    int d = idx >> 18;
    int w = (idx >> 7) & (NW-1);
    int j = idx & 127;
    g_h[d][w][j] = embp[(size_t)feat[w]*Hd + d*HHd + j];
    g_c[d][w][j] = 0.f;
}

__global__ void k_gatherW(const int* __restrict__ wid, const float* __restrict__ embw){
    int idx = blockIdx.x*256 + threadIdx.x;   // NW*256
    int w = idx >> 8, j = idx & 255;
    g_wordx[w][j] = embw[(size_t)wid[w]*256 + j];
}

// ---------------- generic GEMM: C[m][n] = (C0) + (bias0+bias1) + sum_k A[m,k]*B[n,k] ----------------
// M%64==0, N%64==0, K%16==0
__global__ __launch_bounds__(256) void k_gemm(
    const float* __restrict__ A, const float* __restrict__ B,
    const float* __restrict__ bias0, const float* __restrict__ bias1,
    const float* __restrict__ C0, float* __restrict__ C,
    int M, int N, int K)
{
    __shared__ float As[16][68];
    __shared__ float Bs[16][68];
    int bn = blockIdx.x*64, bm = blockIdx.y*64;
    int tid = threadIdx.x;
    int tx = tid & 15, ty = tid >> 4;
    int lr = tid >> 2, lc = (tid & 3) << 2;
    float acc[4][4] = {};
    const float* Ap = A + (size_t)(bm+lr)*K + lc;
    const float* Bp = B + (size_t)(bn+lr)*K + lc;
    for (int k0 = 0; k0 < K; k0 += 16){
        float4 a = *(const float4*)(Ap + k0);
        float4 b = *(const float4*)(Bp + k0);
        As[lc+0][lr]=a.x; As[lc+1][lr]=a.y; As[lc+2][lr]=a.z; As[lc+3][lr]=a.w;
        Bs[lc+0][lr]=b.x; Bs[lc+1][lr]=b.y; Bs[lc+2][lr]=b.z; Bs[lc+3][lr]=b.w;
        __syncthreads();
        #pragma unroll
        for (int k=0;k<16;k++){
            float4 av = *(const float4*)&As[k][ty<<2];
            float4 bv = *(const float4*)&Bs[k][tx<<2];
            float ar[4]={av.x,av.y,av.z,av.w};
            float br[4]={bv.x,bv.y,bv.z,bv.w};
            #pragma unroll
            for (int i=0;i<4;i++)
                #pragma unroll
                for (int j=0;j<4;j++)
                    acc[i][j] += ar[i]*br[j];
        }
        __syncthreads();
    }
    int n0 = bn + (tx<<2);
    float bb[4] = {0.f,0.f,0.f,0.f};
    if (bias0){ bb[0]=bias0[n0]; bb[1]=bias0[n0+1]; bb[2]=bias0[n0+2]; bb[3]=bias0[n0+3]; }
    if (bias1){ bb[0]+=bias1[n0]; bb[1]+=bias1[n0+1]; bb[2]+=bias1[n0+2]; bb[3]+=bias1[n0+3]; }
    #pragma unroll
    for (int i=0;i<4;i++){
        int m = bm + (ty<<2) + i;
        float4 v;
        v.x = acc[i][0]+bb[0]; v.y = acc[i][1]+bb[1];
        v.z = acc[i][2]+bb[2]; v.w = acc[i][3]+bb[3];
        if (C0){
            float4 c0 = *(const float4*)&C0[(size_t)m*N + n0];
            v.x += c0.x; v.y += c0.y; v.z += c0.z; v.w += c0.w;
        }
        *(float4*)&C[(size_t)m*N + n0] = v;
    }
}

// ---------------- LSTM pointwise update (batched char/syl) ----------------
__global__ void k_update(int s, int T){
    int idx = blockIdx.x*256 + threadIdx.x;   // 2*NW*HH
    int d = idx >> 18;
    int w = (idx >> 7) & (NW-1);
    int j = idx & 127;
    const float* gg = &g_gates[d][w][0];
    float i_ = gg[j], f_ = gg[128+j], g_ = gg[256+j], o_ = gg[384+j];
    float c = g_c[d][w][j];
    c = sigf(f_)*c + sigf(i_)*tanhf(g_);
    float h = sigf(o_)*tanhf(c);
    g_c[d][w][j] = c;
    g_h[d][w][j] = h;
    int t = d ? (T-1-s) : s;
    g_out[t][w][d*128 + j] = h;
}

// ---------------- attention score: score[t,w] = sum_g tanh(E[t,w,g])*wv[g] ----------------
__global__ void k_score(int T, const float* __restrict__ wv){
    int gw = blockIdx.x*8 + (threadIdx.x >> 5);
    int lane = threadIdx.x & 31;
    if (gw >= T*NW) return;
    const float* e = &g_E[0][0][0] + (size_t)gw*Hd;
    float a = 0.f;
    #pragma unroll
    for (int i=0;i<8;i++){
        int g = lane + i*32;
        a += tanhf(e[g]) * wv[g];
    }
    #pragma unroll
    for (int o=16;o;o>>=1) a += __shfl_xor_sync(0xffffffffu, a, o);
    if (lane == 0) (&g_score[0][0])[gw] = a;
}

// ---------------- softmax over t + weighted context ----------------
__global__ void k_softctx(int T, int off){
    int w = blockIdx.x, tid = threadIdx.x;    // 256 threads
    __shared__ float sc[TCC];
    if (tid < T) sc[tid] = g_score[tid][w];
    __syncthreads();
    float m = -1e30f;
    for (int t=0;t<T;t++) m = fmaxf(m, sc[t]);
    float den = 0.f, acc = 0.f;
    for (int t=0;t<T;t++){
        float e = expf(sc[t]-m);
        den += e;
        acc += e * g_out[t][w][tid];
    }
    g_wordx[w][off + tid] = acc/den;
}

// ---------------- word-level sequential BiLSTM ----------------
// 2 blocks (fwd/bwd), 512 threads (one gate each). Whh row: 64 weights in smem, 64 in regs.
__global__ __launch_bounds__(512,1) void k_wordrec(
    const float* __restrict__ Whh, const float* __restrict__ PW, float* __restrict__ wout)
{
    extern __shared__ float smem[];
    float* sW  = smem;                // [512][68] padded, weights k=0..63
    float* sh  = smem + 512*68;       // h [128]
    float* scc = sh + 128;            // c [128]
    float* sg  = scc + 128;           // gates [512]
    int dir = blockIdx.x;
    int n = threadIdx.x;
    const float* wrow = Whh + ((size_t)dir*Gd + n)*HHd;
    float4 wr[16];
    #pragma unroll
    for (int k=0;k<16;k++) wr[k] = *(const float4*)&wrow[64 + k*4];
    #pragma unroll
    for (int k=0;k<16;k++) *(float4*)&sW[n*68 + k*4] = *(const float4*)&wrow[k*4];
    if (n < 128){ sh[n] = 0.f; scc[n] = 0.f; }
    const float* PWd = PW + (size_t)dir*NW*Gd;
    __syncthreads();
    for (int s=0;s<NW;s++){
        int t = dir ? (NW-1-s) : s;
        float acc = __ldg(&PWd[t*Gd + n]);
        float a0=0.f, a1=0.f, a2=0.f, a3=0.f;
        #pragma unroll
        for (int k=0;k<16;k++){
            float4 w4 = *(const float4*)&sW[n*68 + k*4];
            float4 h4 = *(const float4*)&sh[k*4];
            a0 += w4.x*h4.x; a1 += w4.y*h4.y; a2 += w4.z*h4.z; a3 += w4.w*h4.w;
        }
        #pragma unroll
        for (int k=0;k<16;k++){
            float4 h4 = *(const float4*)&sh[64 + k*4];
            a0 += wr[k].x*h4.x; a1 += wr[k].y*h4.y; a2 += wr[k].z*h4.z; a3 += wr[k].w*h4.w;
        }
        sg[n] = acc + (a0+a1) + (a2+a3);
        __syncthreads();
        if (n < 128){
            float i_ = sg[n], f_ = sg[128+n], g_ = sg[256+n], o_ = sg[384+n];
            float c = sigf(f_)*scc[n] + sigf(i_)*tanhf(g_);
            float h = sigf(o_)*tanhf(c);
            scc[n] = c; sh[n] = h;
            wout[t*Hd + dir*HHd + n] = h;
        }
        __syncthreads();
    }
}

// ---------------- final linear heads + log_softmax ----------------
__global__ void k_head(const float* __restrict__ wout,
                       const float* __restrict__ Wp, const float* __restrict__ bp,
                       const float* __restrict__ Wn, const float* __restrict__ bn_,
                       float* __restrict__ out)
{
    int w = blockIdx.x, tid = threadIdx.x;    // 64 threads
    __shared__ float h[Hd];
    __shared__ float lg[60];
    for (int i=tid;i<Hd;i+=64) h[i] = wout[w*Hd + i];
    __syncthreads();
    if (tid < 47){
        float a = bp[tid];
        const float* r = Wp + (size_t)tid*Hd;
        for (int k=0;k<Hd;k++) a += h[k]*r[k];
        lg[tid] = a;
    } else if (tid < 60){
        int n = tid-47;
        float a = bn_[n];
        const float* r = Wn + (size_t)n*Hd;
        for (int k=0;k<Hd;k++) a += h[k]*r[k];
        lg[tid] = a;
    }
    __syncthreads();
    if (tid < 47){
        float m = -1e30f;
        for (int i=0;i<47;i++) m = fmaxf(m, lg[i]);
        float s = 0.f;
        for (int i=0;i<47;i++) s += expf(lg[i]-m);
        out[(size_t)w*47 + tid] = lg[tid] - m - logf(s);
    } else if (tid < 60){
        float m = -1e30f;
        for (int i=47;i<60;i++) m = fmaxf(m, lg[i]);
        float s = 0.f;
        for (int i=47;i<60;i++) s += expf(lg[i]-m);
        out[(size_t)NW*47 + (size_t)w*13 + (tid-47)] = lg[tid] - m - logf(s);
    }
}

// ---------------- orchestration ----------------
extern "C" void kernel_launch(void* const* d_in, const int* in_sizes, int n_in,
                              void* d_out, int out_size)
{
    const int*   word_seq = (const int*)  d_in[0];
    const int*   syl_seq  = (const int*)  d_in[1];
    const int*   char_seq = (const int*)  d_in[2];
    const int*   feat_seq = (const int*)  d_in[3];
    const float* emb_char = (const float*)d_in[4];
    const float* emb_syl  = (const float*)d_in[5];
    const float* emb_word = (const float*)d_in[6];
    const float* emb_pref = (const float*)d_in[7];
    const float* aW_c = (const float*)d_in[8];
    const float* ab_c = (const float*)d_in[9];
    const float* aw_c = (const float*)d_in[10];
    const float* aW_s = (const float*)d_in[11];
    const float* ab_s = (const float*)d_in[12];
    const float* aw_s = (const float*)d_in[13];
    const float* cWih = (const float*)d_in[14];
    const float* cWhh = (const float*)d_in[15];
    const float* cbih = (const float*)d_in[16];
    const float* cbhh = (const float*)d_in[17];
    const float* sWih = (const float*)d_in[18];
    const float* sWhh = (const float*)d_in[19];
    const float* sbih = (const float*)d_in[20];
    const float* sbhh = (const float*)d_in[21];
    const float* wWih = (const float*)d_in[22];
    const float* wWhh = (const float*)d_in[23];
    const float* wbih = (const float*)d_in[24];
    const float* wbhh = (const float*)d_in[25];
    const float* Wp = (const float*)d_in[26];
    const float* bp = (const float*)d_in[27];
    const float* Wn = (const float*)d_in[28];
    const float* bn = (const float*)d_in[29];
    float* out = (float*)d_out;

    float *pX, *pP, *pH, *pG, *pOut, *pE, *pWX, *pPW, *pWout;
    cudaGetSymbolAddress((void**)&pX,   g_X);
    cudaGetSymbolAddress((void**)&pP,   g_P);
    cudaGetSymbolAddress((void**)&pH,   g_h);
    cudaGetSymbolAddress((void**)&pG,   g_gates);
    cudaGetSymbolAddress((void**)&pOut, g_out);
    cudaGetSymbolAddress((void**)&pE,   g_E);
    cudaGetSymbolAddress((void**)&pWX,  g_wordx);
    cudaGetSymbolAddress((void**)&pPW,  g_PW);
    cudaGetSymbolAddress((void**)&pWout,g_wout);

    const int wr_smem = (512*68 + 128 + 128 + 512) * 4;  // 142336 B
    cudaFuncSetAttribute(k_wordrec, cudaFuncAttributeMaxDynamicSharedMemorySize, wr_smem);

    // ===== char + syl composition phases =====
    for (int phase = 0; phase < 2; phase++){
        int T            = phase == 0 ? TCC      : TSS;
        const int*   ids = phase == 0 ? char_seq : syl_seq;
        const float* emb = phase == 0 ? emb_char : emb_syl;
        const float* Wih = phase == 0 ? cWih : sWih;
        const float* Whh = phase == 0 ? cWhh : sWhh;
        const float* bih = phase == 0 ? cbih : sbih;
        const float* bhh = phase == 0 ? cbhh : sbhh;
        const float* aW  = phase == 0 ? aW_c : aW_s;
        const float* ab  = phase == 0 ? ab_c : ab_s;
        const float* aw  = phase == 0 ? aw_c : aw_s;
        int off          = phase == 0 ? 256 : 512;
        int M            = T * NW;

        k_init<<<2048, 256>>>(feat_seq, emb_pref);
        k_gatherX<<<(NW*T*64 + 255)/256, 256>>>(ids, emb, T);

        // input projections (both directions)
        for (int d = 0; d < 2; d++){
            k_gemm<<<dim3(Gd/64, M/64), 256>>>(
                pX, Wih + (size_t)d*Gd*64, bih + d*Gd, bhh + d*Gd,
                nullptr, pP + (size_t)d*TCC*NW*Gd, M, Gd, 64);
        }
        // recurrence
        for (int s = 0; s < T; s++){
            for (int d = 0; d < 2; d++){
                int t = d ? (T-1-s) : s;
                k_gemm<<<dim3(Gd/64, NW/64), 256>>>(
                    pH + (size_t)d*NW*HHd, Whh + (size_t)d*Gd*HHd,
                    nullptr, nullptr,
                    pP + ((size_t)d*TCC + t)*NW*Gd,
                    pG + (size_t)d*NW*Gd, NW, Gd, HHd);
            }
            k_update<<<2048, 256>>>(s, T);
        }
        // attention
        k_gemm<<<dim3(Hd/64, M/64), 256>>>(pOut, aW, ab, nullptr, nullptr, pE, M, Hd, Hd);
        k_score<<<(T*NW)/8, 256>>>(T, aw);
        k_softctx<<<NW, 256>>>(T, off);
    }

    // ===== word-level BiLSTM =====
    k_gatherW<<<NW, 256>>>(word_seq, emb_word);
    for (int d = 0; d < 2; d++){
        k_gemm<<<dim3(Gd/64, NW/64), 256>>>(
            pWX, wWih + (size_t)d*Gd*WXD, wbih + d*Gd, wbhh + d*Gd,
            nullptr, pPW + (size_t)d*NW*Gd, NW, Gd, WXD);
    }
    k_wordrec<<<2, 512, wr_smem>>>(wWhh, pPW, pWout);

    // ===== heads =====
    k_head<<<NW, 64>>>(pWout, Wp, bp, Wn, bn, out);
}

// round 3
// speedup vs baseline: 1.3756x; 1.3756x over previous
#include <cuda_runtime.h>
#include <cstdint>
#include <math.h>

#define NW 2048
#define TCC 12
#define TSS 4
#define HHd 128
#define Hd  256
#define Gd  512
#define WXD 768

// ---------------- scratch (device globals; no allocation) ----------------
__device__ float g_X[TCC][NW][64];        // char/syl embeddings, t-major
__device__ float g_P[2][TCC][NW][Gd];     // input projections (gate-permuted layout)
__device__ float g_h2[2][2][NW][HHd];     // [buf][dir] double-buffered h
__device__ float g_c[2][NW][HHd];
__device__ float g_out[TCC][NW][Hd];      // bilstm outputs
__device__ float g_E[TCC][NW][Hd];        // attention energies (pre-tanh)
__device__ float g_score[TCC][NW];
__device__ float g_wordx[NW][WXD];        // [word_emb | char_ctx | syl_ctx]
__device__ float g_PW[2][NW][Gd];         // word LSTM input projections (natural layout)
__device__ float g_wout[NW][Hd];
__device__ float g_WhhP[2][Gd][HHd];      // gate-permuted Whh
__device__ float g_WihP[2][Gd][64];       // gate-permuted Wih
__device__ float g_bP[2][Gd];             // gate-permuted (bih+bhh)

__device__ __forceinline__ float sigf(float x){ return 1.f/(1.f+expf(-x)); }

__device__ __forceinline__ unsigned long long ffma2(unsigned long long a, unsigned long long b, unsigned long long c){
    unsigned long long d;
    asm("fma.rn.f32x2 %0, %1, %2, %3;" : "=l"(d) : "l"(a), "l"(b), "l"(c));
    return d;
}
__device__ __forceinline__ float f2sum(unsigned long long a){
    float lo, hi;
    asm("mov.b64 {%0,%1}, %2;" : "=f"(lo), "=f"(hi) : "l"(a));
    return lo + hi;
}

// ---------------- gather kernels ----------------
__global__ void k_gatherX(const int* __restrict__ ids, const float* __restrict__ emb, int T){
    int idx = blockIdx.x*256 + threadIdx.x;
    int total = NW*T*64;
    if (idx >= total) return;
    int dcol = idx & 63;
    int r = idx >> 6;              // w*T + t
    int t = r % T, w = r / T;
    g_X[t][w][dcol] = emb[(size_t)ids[r]*64 + dcol];
}

__global__ void k_init(const int* __restrict__ feat, const float* __restrict__ embp){
    int idx = blockIdx.x*256 + threadIdx.x;   // 2*NW*HH = 524288
    int d = idx >> 18;
    int w = (idx >> 7) & (NW-1);
    int j = idx & 127;
    g_h2[0][d][w][j] = embp[(size_t)feat[w]*Hd + d*HHd + j];
    g_c[d][w][j] = 0.f;
}

__global__ void k_gatherW(const int* __restrict__ wid, const float* __restrict__ embw){
    int idx = blockIdx.x*256 + threadIdx.x;   // NW*256
    int w = idx >> 8, j = idx & 255;
    g_wordx[w][j] = embw[(size_t)wid[w]*256 + j];
}

// gate-interleave permutation: new row n = 4*j + g  <-  old row g*128 + j
__global__ void k_permW(const float* __restrict__ Wih, const float* __restrict__ Whh,
                        const float* __restrict__ bih, const float* __restrict__ bhh){
    int r = blockIdx.x*256 + threadIdx.x;   // 1024 rows
    if (r >= 1024) return;
    int d = r >> 9, n = r & 511;
    int g = n & 3, j = n >> 2;
    int oldr = g*128 + j;
    const float4* sh_ = (const float4*)(Whh + ((size_t)d*Gd + oldr)*HHd);
    float4* dh = (float4*)&g_WhhP[d][n][0];
    #pragma unroll
    for (int k=0;k<32;k++) dh[k] = sh_[k];
    const float4* si = (const float4*)(Wih + ((size_t)d*Gd + oldr)*64);
    float4* di = (float4*)&g_WihP[d][n][0];
    #pragma unroll
    for (int k=0;k<16;k++) di[k] = si[k];
    g_bP[d][n] = bih[d*Gd + oldr] + bhh[d*Gd + oldr];
}

// ---------------- generic GEMM (z-batched): C = C0 + bias0+bias1 + A@B^T ----------------
__global__ __launch_bounds__(256) void k_gemm(
    const float* __restrict__ A, const float* __restrict__ B,
    const float* __restrict__ bias0, const float* __restrict__ bias1,
    const float* __restrict__ C0, float* __restrict__ C,
    int M, int N, int K,
    long sB, long sBias, long sC0, long sC)
{
    __shared__ float As[16][68];
    __shared__ float Bs[16][68];
    long z = blockIdx.z;
    B += z*sB;
    if (bias0) bias0 += z*sBias;
    if (bias1) bias1 += z*sBias;
    if (C0) C0 += z*sC0;
    C += z*sC;
    int bn = blockIdx.x*64, bm = blockIdx.y*64;
    int tid = threadIdx.x;
    int tx = tid & 15, ty = tid >> 4;
    int lr = tid >> 2, lc = (tid & 3) << 2;
    float acc[4][4] = {};
    const float* Ap = A + (size_t)(bm+lr)*K + lc;
    const float* Bp = B + (size_t)(bn+lr)*K + lc;
    for (int k0 = 0; k0 < K; k0 += 16){
        float4 a = *(const float4*)(Ap + k0);
        float4 b = *(const float4*)(Bp + k0);
        As[lc+0][lr]=a.x; As[lc+1][lr]=a.y; As[lc+2][lr]=a.z; As[lc+3][lr]=a.w;
        Bs[lc+0][lr]=b.x; Bs[lc+1][lr]=b.y; Bs[lc+2][lr]=b.z; Bs[lc+3][lr]=b.w;
        __syncthreads();
        #pragma unroll
        for (int k=0;k<16;k++){
            float4 av = *(const float4*)&As[k][ty<<2];
            float4 bv = *(const float4*)&Bs[k][tx<<2];
            float ar[4]={av.x,av.y,av.z,av.w};
            float br[4]={bv.x,bv.y,bv.z,bv.w};
            #pragma unroll
            for (int i=0;i<4;i++)
                #pragma unroll
                for (int j=0;j<4;j++)
                    acc[i][j] += ar[i]*br[j];
        }
        __syncthreads();
    }
    int n0 = bn + (tx<<2);
    float bb[4] = {0.f,0.f,0.f,0.f};
    if (bias0){ bb[0]=bias0[n0]; bb[1]=bias0[n0+1]; bb[2]=bias0[n0+2]; bb[3]=bias0[n0+3]; }
    if (bias1){ bb[0]+=bias1[n0]; bb[1]+=bias1[n0+1]; bb[2]+=bias1[n0+2]; bb[3]+=bias1[n0+3]; }
    #pragma unroll
    for (int i=0;i<4;i++){
        int m = bm + (ty<<2) + i;
        float4 v;
        v.x = acc[i][0]+bb[0]; v.y = acc[i][1]+bb[1];
        v.z = acc[i][2]+bb[2]; v.w = acc[i][3]+bb[3];
        if (C0){
            float4 c0 = *(const float4*)&C0[(size_t)m*N + n0];
            v.x += c0.x; v.y += c0.y; v.z += c0.z; v.w += c0.w;
        }
        *(float4*)&C[(size_t)m*N + n0] = v;
    }
}

// ---------------- fused recurrence GEMM + LSTM pointwise (gate-permuted) ----------------
// grid (8, 32, 2dirs), block 256. gates = h_prev @ WhhP^T + P[t]; epilogue does LSTM update.
__global__ __launch_bounds__(256) void k_recfused(int s, int T){
    __shared__ float As[16][68];
    __shared__ float Bs[16][68];
    int d = blockIdx.z;
    int t = d ? (T-1-s) : s;
    int buf = s & 1;
    const float* A  = &g_h2[buf][d][0][0];
    const float* B  = &g_WhhP[d][0][0];
    const float* C0 = &g_P[d][t][0][0];
    int bn = blockIdx.x*64, bm = blockIdx.y*64;
    int tid = threadIdx.x;
    int tx = tid & 15, ty = tid >> 4;
    int lr = tid >> 2, lc = (tid & 3) << 2;
    float acc[4][4] = {};
    const float* Ap = A + (size_t)(bm+lr)*HHd + lc;
    const float* Bp = B + (size_t)(bn+lr)*HHd + lc;
    #pragma unroll
    for (int k0 = 0; k0 < HHd; k0 += 16){
        float4 a = *(const float4*)(Ap + k0);
        float4 b = *(const float4*)(Bp + k0);
        As[lc+0][lr]=a.x; As[lc+1][lr]=a.y; As[lc+2][lr]=a.z; As[lc+3][lr]=a.w;
        Bs[lc+0][lr]=b.x; Bs[lc+1][lr]=b.y; Bs[lc+2][lr]=b.z; Bs[lc+3][lr]=b.w;
        __syncthreads();
        #pragma unroll
        for (int k=0;k<16;k++){
            float4 av = *(const float4*)&As[k][ty<<2];
            float4 bv = *(const float4*)&Bs[k][tx<<2];
            float ar[4]={av.x,av.y,av.z,av.w};
            float br[4]={bv.x,bv.y,bv.z,bv.w};
            #pragma unroll
            for (int i=0;i<4;i++)
                #pragma unroll
                for (int j=0;j<4;j++)
                    acc[i][j] += ar[i]*br[j];
        }
        __syncthreads();
    }
    int n0 = bn + (tx<<2);
    int j = n0 >> 2;               // columns n0..n0+3 = gates i,f,g,o of hidden unit j
    #pragma unroll
    for (int i=0;i<4;i++){
        int m = bm + (ty<<2) + i;
        float4 p = *(const float4*)&C0[(size_t)m*Gd + n0];
        float gi = acc[i][0]+p.x, gf = acc[i][1]+p.y, gg = acc[i][2]+p.z, go = acc[i][3]+p.w;
        float c = sigf(gf)*g_c[d][m][j] + sigf(gi)*tanhf(gg);
        float h = sigf(go)*tanhf(c);
        g_c[d][m][j] = c;
        g_h2[buf^1][d][m][j] = h;
        g_out[t][m][d*HHd + j] = h;
    }
}

// ---------------- attention score ----------------
__global__ void k_score(int T, const float* __restrict__ wv){
    int gw = blockIdx.x*8 + (threadIdx.x >> 5);
    int lane = threadIdx.x & 31;
    if (gw >= T*NW) return;
    const float* e = &g_E[0][0][0] + (size_t)gw*Hd;
    float a = 0.f;
    #pragma unroll
    for (int i=0;i<8;i++){
        int g = lane + i*32;
        a += tanhf(e[g]) * wv[g];
    }
    #pragma unroll
    for (int o=16;o;o>>=1) a += __shfl_xor_sync(0xffffffffu, a, o);
    if (lane == 0) (&g_score[0][0])[gw] = a;
}

// ---------------- softmax over t + weighted context ----------------
__global__ void k_softctx(int T, int off){
    int w = blockIdx.x, tid = threadIdx.x;    // 256 threads
    __shared__ float sc[TCC];
    if (tid < T) sc[tid] = g_score[tid][w];
    __syncthreads();
    float m = -1e30f;
    for (int t=0;t<T;t++) m = fmaxf(m, sc[t]);
    float den = 0.f, acc = 0.f;
    for (int t=0;t<T;t++){
        float e = expf(sc[t]-m);
        den += e;
        acc += e * g_out[t][w][tid];
    }
    g_wordx[w][off + tid] = acc/den;
}

// ---------------- word-level sequential BiLSTM (f32x2, weights mostly in regs) ----------------
// 2 blocks (dir), 256 threads. Thread t owns gate rows t and t+256 (natural layout).
// Per row: 104 weights in registers (52 f32x2), 24 weights in smem (stride-28 padded).
__global__ __launch_bounds__(256,1) void k_wordrec(
    const float* __restrict__ Whh, const float* __restrict__ PW, float* __restrict__ wout)
{
    extern __shared__ float smem[];
    float* sW  = smem;                 // [512][28] rows' weights k=104..127 (24 floats used)
    float* sh  = smem + 512*28;        // h [128] (16B aligned: 512*28*4 = 57344)
    float* scc = sh + 128;             // c [128]
    float* sg  = scc + 128;            // gates [512]
    int dir = blockIdx.x;
    int t0  = threadIdx.x;
    int r0 = t0, r1 = t0 + 256;
    const float* row0 = Whh + ((size_t)dir*Gd + r0)*HHd;
    const float* row1 = Whh + ((size_t)dir*Gd + r1)*HHd;

    unsigned long long wa[52], wb[52];
    const unsigned long long* p0 = (const unsigned long long*)row0;
    const unsigned long long* p1 = (const unsigned long long*)row1;
    #pragma unroll
    for (int k=0;k<52;k++){ wa[k] = p0[k]; wb[k] = p1[k]; }
    #pragma unroll
    for (int k=0;k<6;k++){
        ((float4*)&sW[r0*28])[k] = ((const float4*)(row0 + 104))[k];
        ((float4*)&sW[r1*28])[k] = ((const float4*)(row1 + 104))[k];
    }
    if (t0 < 128){ sh[t0] = 0.f; scc[t0] = 0.f; }
    const float* PWd = PW + (size_t)dir*NW*Gd;
    __syncthreads();

    for (int s=0;s<NW;s++){
        int t = dir ? (NW-1-s) : s;
        float pv0 = __ldg(&PWd[(size_t)t*Gd + r0]);
        float pv1 = __ldg(&PWd[(size_t)t*Gd + r1]);
        unsigned long long a0=0ull, a1=0ull, a2=0ull, a3=0ull;
        const ulonglong2* hp = (const ulonglong2*)sh;
        #pragma unroll
        for (int q=0;q<26;q++){
            ulonglong2 h2 = hp[q];            // h[4q..4q+3]
            a0 = ffma2(wa[2*q],   h2.x, a0);
            a1 = ffma2(wa[2*q+1], h2.y, a1);
            a2 = ffma2(wb[2*q],   h2.x, a2);
            a3 = ffma2(wb[2*q+1], h2.y, a3);
        }
        #pragma unroll
        for (int q=0;q<6;q++){
            ulonglong2 h2 = hp[26+q];         // h[104+4q..107+4q]
            ulonglong2 w0 = *(const ulonglong2*)&sW[r0*28 + q*4];
            ulonglong2 w1 = *(const ulonglong2*)&sW[r1*28 + q*4];
            a0 = ffma2(w0.x, h2.x, a0);
            a1 = ffma2(w0.y, h2.y, a1);
            a2 = ffma2(w1.x, h2.x, a2);
            a3 = ffma2(w1.y, h2.y, a3);
        }
        sg[r0] = pv0 + f2sum(a0) + f2sum(a1);
        sg[r1] = pv1 + f2sum(a2) + f2sum(a3);
        __syncthreads();
        if (t0 < 128){
            float i_ = sg[t0], f_ = sg[128+t0], g_ = sg[256+t0], o_ = sg[384+t0];
            float c = sigf(f_)*scc[t0] + sigf(i_)*tanhf(g_);
            float h = sigf(o_)*tanhf(c);
            scc[t0] = c; sh[t0] = h;
            wout[(size_t)t*Hd + dir*HHd + t0] = h;
        }
        __syncthreads();
    }
}

// ---------------- final linear heads + log_softmax ----------------
__global__ void k_head(const float* __restrict__ wout,
                       const float* __restrict__ Wp, const float* __restrict__ bp,
                       const float* __restrict__ Wn, const float* __restrict__ bn_,
                       float* __restrict__ out)
{
    int w = blockIdx.x, tid = threadIdx.x;    // 64 threads
    __shared__ float h[Hd];
    __shared__ float lg[60];
    for (int i=tid;i<Hd;i+=64) h[i] = wout[w*Hd + i];
    __syncthreads();
    if (tid < 47){
        float a = bp[tid];
        const float* r = Wp + (size_t)tid*Hd;
        for (int k=0;k<Hd;k++) a += h[k]*r[k];
        lg[tid] = a;
    } else if (tid < 60){
        int n = tid-47;
        float a = bn_[n];
        const float* r = Wn + (size_t)n*Hd;
        for (int k=0;k<Hd;k++) a += h[k]*r[k];
        lg[tid] = a;
    }
    __syncthreads();
    if (tid < 47){
        float m = -1e30f;
        for (int i=0;i<47;i++) m = fmaxf(m, lg[i]);
        float s = 0.f;
        for (int i=0;i<47;i++) s += expf(lg[i]-m);
        out[(size_t)w*47 + tid] = lg[tid] - m - logf(s);
    } else if (tid < 60){
        float m = -1e30f;
        for (int i=47;i<60;i++) m = fmaxf(m, lg[i]);
        float s = 0.f;
        for (int i=47;i<60;i++) s += expf(lg[i]-m);
        out[(size_t)NW*47 + (size_t)w*13 + (tid-47)] = lg[tid] - m - logf(s);
    }
}

// ---------------- orchestration ----------------
extern "C" void kernel_launch(void* const* d_in, const int* in_sizes, int n_in,
                              void* d_out, int out_size)
{
    const int*   word_seq = (const int*)  d_in[0];
    const int*   syl_seq  = (const int*)  d_in[1];
    const int*   char_seq = (const int*)  d_in[2];
    const int*   feat_seq = (const int*)  d_in[3];
    const float* emb_char = (const float*)d_in[4];
    const float* emb_syl  = (const float*)d_in[5];
    const float* emb_word = (const float*)d_in[6];
    const float* emb_pref = (const float*)d_in[7];
    const float* aW_c = (const float*)d_in[8];
    const float* ab_c = (const float*)d_in[9];
    const float* aw_c = (const float*)d_in[10];
    const float* aW_s = (const float*)d_in[11];
    const float* ab_s = (const float*)d_in[12];
    const float* aw_s = (const float*)d_in[13];
    const float* cWih = (const float*)d_in[14];
    const float* cWhh = (const float*)d_in[15];
    const float* cbih = (const float*)d_in[16];
    const float* cbhh = (const float*)d_in[17];
    const float* sWih = (const float*)d_in[18];
    const float* sWhh = (const float*)d_in[19];
    const float* sbih = (const float*)d_in[20];
    const float* sbhh = (const float*)d_in[21];
    const float* wWih = (const float*)d_in[22];
    const float* wWhh = (const float*)d_in[23];
    const float* wbih = (const float*)d_in[24];
    const float* wbhh = (const float*)d_in[25];
    const float* Wp = (const float*)d_in[26];
    const float* bp = (const float*)d_in[27];
    const float* Wn = (const float*)d_in[28];
    const float* bn = (const float*)d_in[29];
    float* out = (float*)d_out;

    float *pX, *pP, *pE, *pWX, *pPW, *pWout, *pWihP, *pbP;
    cudaGetSymbolAddress((void**)&pX,    g_X);
    cudaGetSymbolAddress((void**)&pP,    g_P);
    cudaGetSymbolAddress((void**)&pE,    g_E);
    cudaGetSymbolAddress((void**)&pWX,   g_wordx);
    cudaGetSymbolAddress((void**)&pPW,   g_PW);
    cudaGetSymbolAddress((void**)&pWout, g_wout);
    cudaGetSymbolAddress((void**)&pWihP, g_WihP);
    cudaGetSymbolAddress((void**)&pbP,   g_bP);
    float *pOut;
    cudaGetSymbolAddress((void**)&pOut,  g_out);

    const int wr_smem = (512*28 + 128 + 128 + 512) * 4;  // 60416 B
    cudaFuncSetAttribute(k_wordrec, cudaFuncAttributeMaxDynamicSharedMemorySize, wr_smem);

    // ===== char + syl composition phases =====
    for (int phase = 0; phase < 2; phase++){
        int T            = phase == 0 ? TCC      : TSS;
        const int*   ids = phase == 0 ? char_seq : syl_seq;
        const float* emb = phase == 0 ? emb_char : emb_syl;
        const float* Wih = phase == 0 ? cWih : sWih;
        const float* Whh = phase == 0 ? cWhh : sWhh;
        const float* bih = phase == 0 ? cbih : sbih;
        const float* bhh = phase == 0 ? cbhh : sbhh;
        const float* aW  = phase == 0 ? aW_c : aW_s;
        const float* ab  = phase == 0 ? ab_c : ab_s;
        const float* aw  = phase == 0 ? aw_c : aw_s;
        int off          = phase == 0 ? 256 : 512;
        int M            = T * NW;

        k_permW<<<4, 256>>>(Wih, Whh, bih, bhh);
        k_init<<<2048, 256>>>(feat_seq, emb_pref);
        k_gatherX<<<(NW*T*64 + 255)/256, 256>>>(ids, emb, T);

        // input projections, both directions in one launch (permuted layout)
        k_gemm<<<dim3(Gd/64, M/64, 2), 256>>>(
            pX, pWihP, pbP, nullptr, nullptr, pP,
            M, Gd, 64,
            (long)Gd*64, (long)Gd, 0L, (long)TCC*NW*Gd);

        // recurrence: fused GEMM + LSTM update, both directions per launch
        for (int s = 0; s < T; s++)
            k_recfused<<<dim3(Gd/64, NW/64, 2), 256>>>(s, T);

        // attention
        k_gemm<<<dim3(Hd/64, M/64, 1), 256>>>(pOut, aW, ab, nullptr, nullptr, pE,
                                              M, Hd, Hd, 0L, 0L, 0L, 0L);
        k_score<<<(T*NW)/8, 256>>>(T, aw);
        k_softctx<<<NW, 256>>>(T, off);
    }

    // ===== word-level BiLSTM =====
    k_gatherW<<<NW, 256>>>(word_seq, emb_word);
    k_gemm<<<dim3(Gd/64, NW/64, 2), 256>>>(
        pWX, wWih, wbih, wbhh, nullptr, pPW,
        NW, Gd, WXD,
        (long)Gd*WXD, (long)Gd, 0L, (long)NW*Gd);
    k_wordrec<<<2, 256, wr_smem>>>(wWhh, pPW, pWout);

    // ===== heads =====
    k_head<<<NW, 64>>>(pWout, Wp, bp, Wn, bn, out);
}

// round 4
// speedup vs baseline: 1.6452x; 1.1960x over previous
#include <cuda_runtime.h>
#include <cstdint>
#include <math.h>

#define NW 2048
#define TCC 12
#define TSS 4
#define HHd 128
#define Hd  256
#define Gd  512
#define WXD 768

typedef unsigned long long ull;

// ---------------- scratch (device globals; no allocation) ----------------
__device__ float g_X[TCC][NW][64];        // char/syl embeddings, t-major
__device__ float g_P[2][TCC][NW][Gd];     // input projections (gate-permuted layout)
__device__ float g_h2[2][2][NW][HHd];     // [buf][dir] double-buffered h
__device__ float g_c[2][NW][HHd];
__device__ float g_out[TCC][NW][Hd];      // bilstm outputs
__device__ float g_E[TCC][NW][Hd];        // attention energies (pre-tanh)
__device__ float g_score[TCC][NW];
__device__ float g_wordx[NW][WXD];        // [word_emb | char_ctx | syl_ctx]
__device__ float g_PW[2][NW][Gd];         // word LSTM input projections (natural layout)
__device__ float g_wout[NW][Hd];
__device__ float g_WhhP[2][Gd][HHd];      // gate-permuted Whh
__device__ float g_WihP[2][Gd][64];       // gate-permuted Wih
__device__ float g_bP[2][Gd];             // gate-permuted (bih+bhh)

// ---------------- fast math helpers ----------------
__device__ __forceinline__ float tanha(float x){
    float y; asm("tanh.approx.f32 %0, %1;" : "=f"(y) : "f"(x)); return y;
}
__device__ __forceinline__ float sigfast(float x){
    return fmaf(tanha(0.5f*x), 0.5f, 0.5f);
}
__device__ __forceinline__ ull ffma2(ull a, ull b, ull c){
    ull d;
    asm("fma.rn.f32x2 %0, %1, %2, %3;" : "=l"(d) : "l"(a), "l"(b), "l"(c));
    return d;
}
__device__ __forceinline__ ull pack2(float lo, float hi){
    ull d; asm("mov.b64 %0, {%1, %2};" : "=l"(d) : "f"(lo), "f"(hi)); return d;
}
__device__ __forceinline__ void unpack2(ull a, float& lo, float& hi){
    asm("mov.b64 {%0, %1}, %2;" : "=f"(lo), "=f"(hi) : "l"(a));
}
__device__ __forceinline__ float f2sum(ull a){
    float lo, hi; unpack2(a, lo, hi); return lo + hi;
}

// ---------------- gather kernels ----------------
__global__ void k_gatherX(const int* __restrict__ ids, const float* __restrict__ emb, int T){
    int idx = blockIdx.x*256 + threadIdx.x;
    int total = NW*T*64;
    if (idx >= total) return;
    int dcol = idx & 63;
    int r = idx >> 6;              // w*T + t
    int t = r % T, w = r / T;
    g_X[t][w][dcol] = emb[(size_t)ids[r]*64 + dcol];
}

__global__ void k_init(const int* __restrict__ feat, const float* __restrict__ embp){
    int idx = blockIdx.x*256 + threadIdx.x;   // 2*NW*HH = 524288
    int d = idx >> 18;
    int w = (idx >> 7) & (NW-1);
    int j = idx & 127;
    g_h2[0][d][w][j] = embp[(size_t)feat[w]*Hd + d*HHd + j];
    g_c[d][w][j] = 0.f;
}

__global__ void k_gatherW(const int* __restrict__ wid, const float* __restrict__ embw){
    int idx = blockIdx.x*256 + threadIdx.x;   // NW*256
    int w = idx >> 8, j = idx & 255;
    g_wordx[w][j] = embw[(size_t)wid[w]*256 + j];
}

// gate-interleave permutation: new row n = 4*j + g  <-  old row g*128 + j
__global__ void k_permW(const float* __restrict__ Wih, const float* __restrict__ Whh,
                        const float* __restrict__ bih, const float* __restrict__ bhh){
    int r = blockIdx.x*256 + threadIdx.x;   // 1024 rows
    if (r >= 1024) return;
    int d = r >> 9, n = r & 511;
    int g = n & 3, j = n >> 2;
    int oldr = g*128 + j;
    const float4* sh_ = (const float4*)(Whh + ((size_t)d*Gd + oldr)*HHd);
    float4* dh = (float4*)&g_WhhP[d][n][0];
    #pragma unroll
    for (int k=0;k<32;k++) dh[k] = sh_[k];
    const float4* si = (const float4*)(Wih + ((size_t)d*Gd + oldr)*64);
    float4* di = (float4*)&g_WihP[d][n][0];
    #pragma unroll
    for (int k=0;k<16;k++) di[k] = si[k];
    g_bP[d][n] = bih[d*Gd + oldr] + bhh[d*Gd + oldr];
}

// ---------------- generic GEMM (z-batched, double-buffered, f32x2): C = C0 + bias + A@B^T ----
__global__ __launch_bounds__(256) void k_gemm(
    const float* __restrict__ A, const float* __restrict__ B,
    const float* __restrict__ bias0, const float* __restrict__ bias1,
    const float* __restrict__ C0, float* __restrict__ C,
    int M, int N, int K,
    long sB, long sBias, long sC0, long sC)
{
    __shared__ __align__(16) float As[2][16][68];
    __shared__ __align__(16) float Bs[2][16][68];
    long z = blockIdx.z;
    B += z*sB;
    if (bias0) bias0 += z*sBias;
    if (bias1) bias1 += z*sBias;
    if (C0) C0 += z*sC0;
    C += z*sC;
    int bn = blockIdx.x*64, bm = blockIdx.y*64;
    int tid = threadIdx.x;
    int tx = tid & 15, ty = tid >> 4;
    int lr = tid >> 2, lc = (tid & 3) << 2;
    const float* Ap = A + (size_t)(bm+lr)*K + lc;
    const float* Bp = B + (size_t)(bn+lr)*K + lc;

    {   // prime buffer 0
        float4 a = *(const float4*)Ap;
        float4 b = *(const float4*)Bp;
        As[0][lc+0][lr]=a.x; As[0][lc+1][lr]=a.y; As[0][lc+2][lr]=a.z; As[0][lc+3][lr]=a.w;
        Bs[0][lc+0][lr]=b.x; Bs[0][lc+1][lr]=b.y; Bs[0][lc+2][lr]=b.z; Bs[0][lc+3][lr]=b.w;
    }
    __syncthreads();

    ull acc[4][2] = {};
    int buf = 0;
    for (int k0 = 16; ; k0 += 16){
        bool more = (k0 < K);
        float4 an, bn2;
        if (more){ an = *(const float4*)(Ap + k0); bn2 = *(const float4*)(Bp + k0); }
        #pragma unroll
        for (int k=0;k<16;k++){
            float4 av = *(const float4*)&As[buf][k][ty<<2];
            ulonglong2 bv = *(const ulonglong2*)&Bs[buf][k][tx<<2];
            ull a0 = pack2(av.x, av.x);
            ull a1 = pack2(av.y, av.y);
            ull a2 = pack2(av.z, av.z);
            ull a3 = pack2(av.w, av.w);
            acc[0][0]=ffma2(a0,bv.x,acc[0][0]); acc[0][1]=ffma2(a0,bv.y,acc[0][1]);
            acc[1][0]=ffma2(a1,bv.x,acc[1][0]); acc[1][1]=ffma2(a1,bv.y,acc[1][1]);
            acc[2][0]=ffma2(a2,bv.x,acc[2][0]); acc[2][1]=ffma2(a2,bv.y,acc[2][1]);
            acc[3][0]=ffma2(a3,bv.x,acc[3][0]); acc[3][1]=ffma2(a3,bv.y,acc[3][1]);
        }
        if (!more) break;
        int nb = buf ^ 1;
        As[nb][lc+0][lr]=an.x;  As[nb][lc+1][lr]=an.y;  As[nb][lc+2][lr]=an.z;  As[nb][lc+3][lr]=an.w;
        Bs[nb][lc+0][lr]=bn2.x; Bs[nb][lc+1][lr]=bn2.y; Bs[nb][lc+2][lr]=bn2.z; Bs[nb][lc+3][lr]=bn2.w;
        __syncthreads();
        buf = nb;
    }

    int n0 = bn + (tx<<2);
    float bb[4] = {0.f,0.f,0.f,0.f};
    if (bias0){ bb[0]=bias0[n0]; bb[1]=bias0[n0+1]; bb[2]=bias0[n0+2]; bb[3]=bias0[n0+3]; }
    if (bias1){ bb[0]+=bias1[n0]; bb[1]+=bias1[n0+1]; bb[2]+=bias1[n0+2]; bb[3]+=bias1[n0+3]; }
    #pragma unroll
    for (int i=0;i<4;i++){
        int m = bm + (ty<<2) + i;
        float c0v,c1v,c2v,c3v;
        unpack2(acc[i][0], c0v, c1v);
        unpack2(acc[i][1], c2v, c3v);
        float4 v;
        v.x = c0v+bb[0]; v.y = c1v+bb[1]; v.z = c2v+bb[2]; v.w = c3v+bb[3];
        if (C0){
            float4 c0 = *(const float4*)&C0[(size_t)m*N + n0];
            v.x += c0.x; v.y += c0.y; v.z += c0.z; v.w += c0.w;
        }
        *(float4*)&C[(size_t)m*N + n0] = v;
    }
}

// ---------------- fused recurrence GEMM + LSTM pointwise (gate-permuted) ----------------
__global__ __launch_bounds__(256) void k_recfused(int s, int T){
    __shared__ __align__(16) float As[2][16][68];
    __shared__ __align__(16) float Bs[2][16][68];
    int d = blockIdx.z;
    int t = d ? (T-1-s) : s;
    int buf0 = s & 1;
    const float* A  = &g_h2[buf0][d][0][0];
    const float* B  = &g_WhhP[d][0][0];
    const float* C0 = &g_P[d][t][0][0];
    int bn = blockIdx.x*64, bm = blockIdx.y*64;
    int tid = threadIdx.x;
    int tx = tid & 15, ty = tid >> 4;
    int lr = tid >> 2, lc = (tid & 3) << 2;
    const float* Ap = A + (size_t)(bm+lr)*HHd + lc;
    const float* Bp = B + (size_t)(bn+lr)*HHd + lc;

    {
        float4 a = *(const float4*)Ap;
        float4 b = *(const float4*)Bp;
        As[0][lc+0][lr]=a.x; As[0][lc+1][lr]=a.y; As[0][lc+2][lr]=a.z; As[0][lc+3][lr]=a.w;
        Bs[0][lc+0][lr]=b.x; Bs[0][lc+1][lr]=b.y; Bs[0][lc+2][lr]=b.z; Bs[0][lc+3][lr]=b.w;
    }
    __syncthreads();

    ull acc[4][2] = {};
    int buf = 0;
    #pragma unroll
    for (int k0 = 16; ; k0 += 16){
        bool more = (k0 < HHd);
        float4 an, bn2;
        if (more){ an = *(const float4*)(Ap + k0); bn2 = *(const float4*)(Bp + k0); }
        #pragma unroll
        for (int k=0;k<16;k++){
            float4 av = *(const float4*)&As[buf][k][ty<<2];
            ulonglong2 bv = *(const ulonglong2*)&Bs[buf][k][tx<<2];
            ull a0 = pack2(av.x, av.x);
            ull a1 = pack2(av.y, av.y);
            ull a2 = pack2(av.z, av.z);
            ull a3 = pack2(av.w, av.w);
            acc[0][0]=ffma2(a0,bv.x,acc[0][0]); acc[0][1]=ffma2(a0,bv.y,acc[0][1]);
            acc[1][0]=ffma2(a1,bv.x,acc[1][0]); acc[1][1]=ffma2(a1,bv.y,acc[1][1]);
            acc[2][0]=ffma2(a2,bv.x,acc[2][0]); acc[2][1]=ffma2(a2,bv.y,acc[2][1]);
            acc[3][0]=ffma2(a3,bv.x,acc[3][0]); acc[3][1]=ffma2(a3,bv.y,acc[3][1]);
        }
        if (!more) break;
        int nb = buf ^ 1;
        As[nb][lc+0][lr]=an.x;  As[nb][lc+1][lr]=an.y;  As[nb][lc+2][lr]=an.z;  As[nb][lc+3][lr]=an.w;
        Bs[nb][lc+0][lr]=bn2.x; Bs[nb][lc+1][lr]=bn2.y; Bs[nb][lc+2][lr]=bn2.z; Bs[nb][lc+3][lr]=bn2.w;
        __syncthreads();
        buf = nb;
    }

    int n0 = bn + (tx<<2);
    int j = n0 >> 2;               // columns n0..n0+3 = gates i,f,g,o of hidden unit j
    #pragma unroll
    for (int i=0;i<4;i++){
        int m = bm + (ty<<2) + i;
        float4 p = *(const float4*)&C0[(size_t)m*Gd + n0];
        float gi,gf,gg,go;
        unpack2(acc[i][0], gi, gf);
        unpack2(acc[i][1], gg, go);
        gi += p.x; gf += p.y; gg += p.z; go += p.w;
        float c = sigfast(gf)*g_c[d][m][j] + sigfast(gi)*tanha(gg);
        float h = sigfast(go)*tanha(c);
        g_c[d][m][j] = c;
        g_h2[buf0^1][d][m][j] = h;
        g_out[t][m][d*HHd + j] = h;
    }
}

// ---------------- attention score ----------------
__global__ void k_score(int T, const float* __restrict__ wv){
    int gw = blockIdx.x*8 + (threadIdx.x >> 5);
    int lane = threadIdx.x & 31;
    if (gw >= T*NW) return;
    const float* e = &g_E[0][0][0] + (size_t)gw*Hd;
    float a = 0.f;
    #pragma unroll
    for (int i=0;i<8;i++){
        int g = lane + i*32;
        a += tanha(e[g]) * wv[g];
    }
    #pragma unroll
    for (int o=16;o;o>>=1) a += __shfl_xor_sync(0xffffffffu, a, o);
    if (lane == 0) (&g_score[0][0])[gw] = a;
}

// ---------------- softmax over t + weighted context ----------------
__global__ void k_softctx(int T, int off){
    int w = blockIdx.x, tid = threadIdx.x;    // 256 threads
    __shared__ float sc[TCC];
    if (tid < T) sc[tid] = g_score[tid][w];
    __syncthreads();
    float m = -1e30f;
    for (int t=0;t<T;t++) m = fmaxf(m, sc[t]);
    float den = 0.f, acc = 0.f;
    for (int t=0;t<T;t++){
        float e = expf(sc[t]-m);
        den += e;
        acc += e * g_out[t][w][tid];
    }
    g_wordx[w][off + tid] = acc/den;
}

// ---------------- word-level sequential BiLSTM (f32x2, weights mostly in regs) ----------------
// 2 blocks (dir), 256 threads. Thread t owns gate rows t and t+256 (natural layout).
// Per row: 104 weights in registers (52 f32x2), 24 weights in smem (stride-28 padded).
__global__ __launch_bounds__(256,1) void k_wordrec(
    const float* __restrict__ Whh, const float* __restrict__ PW, float* __restrict__ wout)
{
    extern __shared__ float smem[];
    float* sW  = smem;                 // [512][28] rows' weights k=104..127 (24 floats used)
    float* sh  = smem + 512*28;        // h [128] (16B aligned: 512*28*4 = 57344)
    float* scc = sh + 128;             // c [128]
    float* sg  = scc + 128;            // gates [512]
    int dir = blockIdx.x;
    int t0  = threadIdx.x;
    int r0 = t0, r1 = t0 + 256;
    const float* row0 = Whh + ((size_t)dir*Gd + r0)*HHd;
    const float* row1 = Whh + ((size_t)dir*Gd + r1)*HHd;

    ull wa[52], wb[52];
    const ull* p0 = (const ull*)row0;
    const ull* p1 = (const ull*)row1;
    #pragma unroll
    for (int k=0;k<52;k++){ wa[k] = p0[k]; wb[k] = p1[k]; }
    #pragma unroll
    for (int k=0;k<6;k++){
        ((float4*)&sW[r0*28])[k] = ((const float4*)(row0 + 104))[k];
        ((float4*)&sW[r1*28])[k] = ((const float4*)(row1 + 104))[k];
    }
    if (t0 < 128){ sh[t0] = 0.f; scc[t0] = 0.f; }
    const float* PWd = PW + (size_t)dir*NW*Gd;
    __syncthreads();

    for (int s=0;s<NW;s++){
        int t = dir ? (NW-1-s) : s;
        float pv0 = __ldg(&PWd[(size_t)t*Gd + r0]);
        float pv1 = __ldg(&PWd[(size_t)t*Gd + r1]);
        ull a0=0ull, a1=0ull, a2=0ull, a3=0ull;
        const ulonglong2* hp = (const ulonglong2*)sh;
        #pragma unroll
        for (int q=0;q<26;q++){
            ulonglong2 h2 = hp[q];            // h[4q..4q+3]
            a0 = ffma2(wa[2*q],   h2.x, a0);
            a1 = ffma2(wa[2*q+1], h2.y, a1);
            a2 = ffma2(wb[2*q],   h2.x, a2);
            a3 = ffma2(wb[2*q+1], h2.y, a3);
        }
        #pragma unroll
        for (int q=0;q<6;q++){
            ulonglong2 h2 = hp[26+q];         // h[104+4q..107+4q]
            ulonglong2 w0 = *(const ulonglong2*)&sW[r0*28 + q*4];
            ulonglong2 w1 = *(const ulonglong2*)&sW[r1*28 + q*4];
            a0 = ffma2(w0.x, h2.x, a0);
            a1 = ffma2(w0.y, h2.y, a1);
            a2 = ffma2(w1.x, h2.x, a2);
            a3 = ffma2(w1.y, h2.y, a3);
        }
        sg[r0] = pv0 + f2sum(a0) + f2sum(a1);
        sg[r1] = pv1 + f2sum(a2) + f2sum(a3);
        __syncthreads();
        if (t0 < 128){
            float i_ = sg[t0], f_ = sg[128+t0], g_ = sg[256+t0], o_ = sg[384+t0];
            float c = sigfast(f_)*scc[t0] + sigfast(i_)*tanha(g_);
            float h = sigfast(o_)*tanha(c);
            scc[t0] = c; sh[t0] = h;
            wout[(size_t)t*Hd + dir*HHd + t0] = h;
        }
        __syncthreads();
    }
}

// ---------------- final linear heads + log_softmax ----------------
__global__ void k_head(const float* __restrict__ wout,
                       const float* __restrict__ Wp, const float* __restrict__ bp,
                       const float* __restrict__ Wn, const float* __restrict__ bn_,
                       float* __restrict__ out)
{
    int w = blockIdx.x, tid = threadIdx.x;    // 64 threads
    __shared__ float h[Hd];
    __shared__ float lg[60];
    for (int i=tid;i<Hd;i+=64) h[i] = wout[w*Hd + i];
    __syncthreads();
    if (tid < 47){
        float a = bp[tid];
        const float* r = Wp + (size_t)tid*Hd;
        for (int k=0;k<Hd;k++) a += h[k]*r[k];
        lg[tid] = a;
    } else if (tid < 60){
        int n = tid-47;
        float a = bn_[n];
        const float* r = Wn + (size_t)n*Hd;
        for (int k=0;k<Hd;k++) a += h[k]*r[k];
        lg[tid] = a;
    }
    __syncthreads();
    if (tid < 47){
        float m = -1e30f;
        for (int i=0;i<47;i++) m = fmaxf(m, lg[i]);
        float s = 0.f;
        for (int i=0;i<47;i++) s += expf(lg[i]-m);
        out[(size_t)w*47 + tid] = lg[tid] - m - logf(s);
    } else if (tid < 60){
        float m = -1e30f;
        for (int i=47;i<60;i++) m = fmaxf(m, lg[i]);
        float s = 0.f;
        for (int i=47;i<60;i++) s += expf(lg[i]-m);
        out[(size_t)NW*47 + (size_t)w*13 + (tid-47)] = lg[tid] - m - logf(s);
    }
}

// ---------------- orchestration ----------------
extern "C" void kernel_launch(void* const* d_in, const int* in_sizes, int n_in,
                              void* d_out, int out_size)
{
    const int*   word_seq = (const int*)  d_in[0];
    const int*   syl_seq  = (const int*)  d_in[1];
    const int*   char_seq = (const int*)  d_in[2];
    const int*   feat_seq = (const int*)  d_in[3];
    const float* emb_char = (const float*)d_in[4];
    const float* emb_syl  = (const float*)d_in[5];
    const float* emb_word = (const float*)d_in[6];
    const float* emb_pref = (const float*)d_in[7];
    const float* aW_c = (const float*)d_in[8];
    const float* ab_c = (const float*)d_in[9];
    const float* aw_c = (const float*)d_in[10];
    const float* aW_s = (const float*)d_in[11];
    const float* ab_s = (const float*)d_in[12];
    const float* aw_s = (const float*)d_in[13];
    const float* cWih = (const float*)d_in[14];
    const float* cWhh = (const float*)d_in[15];
    const float* cbih = (const float*)d_in[16];
    const float* cbhh = (const float*)d_in[17];
    const float* sWih = (const float*)d_in[18];
    const float* sWhh = (const float*)d_in[19];
    const float* sbih = (const float*)d_in[20];
    const float* sbhh = (const float*)d_in[21];
    const float* wWih = (const float*)d_in[22];
    const float* wWhh = (const float*)d_in[23];
    const float* wbih = (const float*)d_in[24];
    const float* wbhh = (const float*)d_in[25];
    const float* Wp = (const float*)d_in[26];
    const float* bp = (const float*)d_in[27];
    const float* Wn = (const float*)d_in[28];
    const float* bn = (const float*)d_in[29];
    float* out = (float*)d_out;

    float *pX, *pP, *pE, *pWX, *pPW, *pWout, *pWihP, *pbP, *pOut;
    cudaGetSymbolAddress((void**)&pX,    g_X);
    cudaGetSymbolAddress((void**)&pP,    g_P);
    cudaGetSymbolAddress((void**)&pE,    g_E);
    cudaGetSymbolAddress((void**)&pWX,   g_wordx);
    cudaGetSymbolAddress((void**)&pPW,   g_PW);
    cudaGetSymbolAddress((void**)&pWout, g_wout);
    cudaGetSymbolAddress((void**)&pWihP, g_WihP);
    cudaGetSymbolAddress((void**)&pbP,   g_bP);
    cudaGetSymbolAddress((void**)&pOut,  g_out);

    const int wr_smem = (512*28 + 128 + 128 + 512) * 4;  // 60416 B
    cudaFuncSetAttribute(k_wordrec, cudaFuncAttributeMaxDynamicSharedMemorySize, wr_smem);

    // ===== char + syl composition phases =====
    for (int phase = 0; phase < 2; phase++){
        int T            = phase == 0 ? TCC      : TSS;
        const int*   ids = phase == 0 ? char_seq : syl_seq;
        const float* emb = phase == 0 ? emb_char : emb_syl;
        const float* Wih = phase == 0 ? cWih : sWih;
        const float* Whh = phase == 0 ? cWhh : sWhh;
        const float* bih = phase == 0 ? cbih : sbih;
        const float* bhh = phase == 0 ? cbhh : sbhh;
        const float* aW  = phase == 0 ? aW_c : aW_s;
        const float* ab  = phase == 0 ? ab_c : ab_s;
        const float* aw  = phase == 0 ? aw_c : aw_s;
        int off          = phase == 0 ? 256 : 512;
        int M            = T * NW;

        k_permW<<<4, 256>>>(Wih, Whh, bih, bhh);
        k_init<<<2048, 256>>>(feat_seq, emb_pref);
        k_gatherX<<<(NW*T*64 + 255)/256, 256>>>(ids, emb, T);

        // input projections, both directions in one launch (permuted layout)
        k_gemm<<<dim3(Gd/64, M/64, 2), 256>>>(
            pX, pWihP, pbP, nullptr, nullptr, pP,
            M, Gd, 64,
            (long)Gd*64, (long)Gd, 0L, (long)TCC*NW*Gd);

        // recurrence: fused GEMM + LSTM update, both directions per launch
        for (int s = 0; s < T; s++)
            k_recfused<<<dim3(Gd/64, NW/64, 2), 256>>>(s, T);

        // attention
        k_gemm<<<dim3(Hd/64, M/64, 1), 256>>>(pOut, aW, ab, nullptr, nullptr, pE,
                                              M, Hd, Hd, 0L, 0L, 0L, 0L);
        k_score<<<(T*NW)/8, 256>>>(T, aw);
        k_softctx<<<NW, 256>>>(T, off);
    }

    // ===== word-level BiLSTM =====
    k_gatherW<<<NW, 256>>>(word_seq, emb_word);
    k_gemm<<<dim3(Gd/64, NW/64, 2), 256>>>(
        pWX, wWih, wbih, wbhh, nullptr, pPW,
        NW, Gd, WXD,
        (long)Gd*WXD, (long)Gd, 0L, (long)NW*Gd);
    k_wordrec<<<2, 256, wr_smem>>>(wWhh, pPW, pWout);

    // ===== heads =====
    k_head<<<NW, 64>>>(pWout, Wp, bp, Wn, bn, out);
}